// round 2
// baseline (speedup 1.0000x reference)
#include <cuda_runtime.h>
#include <cuda_fp16.h>
#include <cstdint>

// ---------------------------------------------------------------------------
// Problem constants
// ---------------------------------------------------------------------------
#define BATCH   8
#define TSTEPS  512
#define NEMBD   512
#define NHID    1024
#define VOCAB   32000
#define KTOT    (NEMBD + NHID)          // 1536
#define NROWS   (BATCH * TSTEPS)        // 4096

// GRU persistent kernel config
#define GRU_BLOCKS   128                // each owns 8 hidden columns
#define GRU_THREADS  256                // 8 warps, K split across warps
#define XH_STRIDE    1540               // 1536 + 4 pad

// SMEM layout (floats)
#define WSM_FLOATS   (KTOT * 24)        // 36864 : [k][24] (z:0-7, r:8-15, h:16-23)
#define XH_FLOATS    (BATCH * XH_STRIDE)// 12320
#define PBUF_FLOATS  (8 * 8 * 16)       // 1024
#define ZSM_FLOATS   64
#define BSM_FLOATS   24
#define GRU_SMEM_FLOATS (WSM_FLOATS + XH_FLOATS + PBUF_FLOATS + ZSM_FLOATS + BSM_FLOATS)
#define GRU_SMEM_BYTES  (GRU_SMEM_FLOATS * 4)   // 201,184 B

// ---------------------------------------------------------------------------
// Device scratch (allocation-free rule: __device__ globals).
// NOTE: these are referenced either (a) directly inside device code, or
// (b) on host ONLY via cudaGetSymbolAddress — never by host-side name decay
// (which yields the host shadow address; ATS on GB300 makes that silently
// "work" by writing host memory — the R1 bug).
// ---------------------------------------------------------------------------
__device__ float               g_h[BATCH * NHID];           // carry h
__device__ float               g_rh[BATCH * NHID];          // r*h broadcast
__device__ __half              g_hs[(size_t)NROWS * NHID];  // hidden states (fp16)
__device__ __half              g_wlm[(size_t)NHID * VOCAB]; // lm head weights fp16
__device__ unsigned long long  g_barrier_ctr;               // cumulative grid barrier
__device__ float               g_logits_fb[(size_t)NROWS * VOCAB]; // fallback logits

// ---------------------------------------------------------------------------
// Lightweight grid barrier (all 128 blocks co-resident; cumulative counter,
// replay-safe across graph launches).
// ---------------------------------------------------------------------------
__device__ __forceinline__ void grid_barrier() {
    __syncthreads();
    if (threadIdx.x == 0) {
        __threadfence();
        unsigned long long arr = atomicAdd(&g_barrier_ctr, 1ULL) + 1ULL;
        unsigned long long nb  = (unsigned long long)gridDim.x;
        unsigned long long target = ((arr + nb - 1ULL) / nb) * nb;
        for (;;) {
            unsigned long long cur;
            asm volatile("ld.volatile.global.u64 %0, [%1];" : "=l"(cur) : "l"(&g_barrier_ctr));
            if (cur >= target) break;
        }
        __threadfence();
    }
    __syncthreads();
}

// ---------------------------------------------------------------------------
// Gate dot-product phase: 8 warps split K=1536 (192 each). lane = (ksub<<3)|b.
// ---------------------------------------------------------------------------
template<int NC, int COFF>
__device__ __forceinline__ void gate_phase(const float* __restrict__ wsm,
                                           const float* __restrict__ xh_s,
                                           float* __restrict__ pbuf,
                                           int warp, int lane) {
    const int b    = lane & 7;
    const int ksub = lane >> 3;
    float acc[NC];
#pragma unroll
    for (int j = 0; j < NC; j++) acc[j] = 0.f;
    const int kbase = warp * 192;
#pragma unroll 8
    for (int i = 0; i < 48; i++) {
        int k = kbase + i * 4 + ksub;
        float xv = xh_s[b * XH_STRIDE + k];
        const float* wr = wsm + k * 24 + COFF;
#pragma unroll
        for (int v = 0; v < NC / 4; v++) {
            float4 wv = *(const float4*)(wr + v * 4);
            acc[v * 4 + 0] += xv * wv.x;
            acc[v * 4 + 1] += xv * wv.y;
            acc[v * 4 + 2] += xv * wv.z;
            acc[v * 4 + 3] += xv * wv.w;
        }
    }
#pragma unroll
    for (int j = 0; j < NC; j++) {
        acc[j] += __shfl_xor_sync(0xffffffffu, acc[j], 8);
        acc[j] += __shfl_xor_sync(0xffffffffu, acc[j], 16);
    }
    if (ksub == 0) {
#pragma unroll
        for (int j = 0; j < NC; j++) pbuf[warp * 128 + b * 16 + j] = acc[j];
    }
}

// ---------------------------------------------------------------------------
// Persistent GRU kernel. Block s owns hidden cols [s*8, s*8+8).
// Globals g_h / g_rh / g_hs / g_barrier_ctr referenced directly (device code).
// ---------------------------------------------------------------------------
__global__ void __launch_bounds__(GRU_THREADS, 1)
gru_kernel(const int* __restrict__ idx, const float* __restrict__ wte,
           const float* __restrict__ start,
           const float* __restrict__ Wz, const float* __restrict__ bz,
           const float* __restrict__ Wr, const float* __restrict__ br,
           const float* __restrict__ Wh, const float* __restrict__ bh) {
    extern __shared__ float smem[];
    float* wsm  = smem;
    float* xh_s = wsm + WSM_FLOATS;
    float* pbuf = xh_s + XH_FLOATS;
    float* zsm  = pbuf + PBUF_FLOATS;
    float* bsm  = zsm + ZSM_FLOATS;

    const int tid     = threadIdx.x;
    const int warp    = tid >> 5;
    const int lane    = tid & 31;
    const int colbase = blockIdx.x * 8;

    for (int i = tid; i < KTOT * 8; i += GRU_THREADS) {
        int k = i >> 3, j = i & 7;
        wsm[k * 24 + j]      = Wz[k * NHID + colbase + j];
        wsm[k * 24 + 8 + j]  = Wr[k * NHID + colbase + j];
        wsm[k * 24 + 16 + j] = Wh[k * NHID + colbase + j];
    }
    if (tid < 8) {
        bsm[tid]      = bz[colbase + tid];
        bsm[8 + tid]  = br[colbase + tid];
        bsm[16 + tid] = bh[colbase + tid];
    }

    const float4* wte4   = (const float4*)wte;
    const float4* start4 = (const float4*)start;
    const float4* h4     = (const float4*)g_h;
    const float4* rh4    = (const float4*)g_rh;

    for (int t = 0; t < TSTEPS; ++t) {
        // stage x_t (embedding gather)
        for (int i = tid; i < 1024; i += GRU_THREADS) {
            int b = i >> 7, j = i & 127;
            int tok = idx[b * TSTEPS + t];
            *(float4*)&xh_s[b * XH_STRIDE + j * 4] = wte4[(size_t)tok * 128 + j];
        }
        // stage h
        if (t == 0) {
            for (int i = tid; i < 2048; i += GRU_THREADS) {
                int b = i >> 8, j = i & 255;
                *(float4*)&xh_s[b * XH_STRIDE + NEMBD + j * 4] = start4[j];
            }
        } else {
            for (int i = tid; i < 2048; i += GRU_THREADS) {
                int b = i >> 8, j = i & 255;
                *(float4*)&xh_s[b * XH_STRIDE + NEMBD + j * 4] = h4[b * 256 + j];
            }
        }
        __syncthreads();

        // ---- Phase A: z and r ----
        gate_phase<16, 0>(wsm, xh_s, pbuf, warp, lane);
        __syncthreads();
        if (tid < 128) {
            int b = tid >> 4, jj = tid & 15;
            float s = 0.f;
#pragma unroll
            for (int w = 0; w < 8; w++) s += pbuf[w * 128 + b * 16 + jj];
            int j = jj & 7;
            if (jj < 8) {
                float z = 1.f / (1.f + __expf(-(s + bsm[j])));
                zsm[b * 8 + j] = z;
            } else {
                float r = 1.f / (1.f + __expf(-(s + bsm[8 + j])));
                g_rh[b * NHID + colbase + j] = r * xh_s[b * XH_STRIDE + NEMBD + colbase + j];
            }
        }
        grid_barrier();

        // stage r*h
        for (int i = tid; i < 2048; i += GRU_THREADS) {
            int b = i >> 8, j = i & 255;
            *(float4*)&xh_s[b * XH_STRIDE + NEMBD + j * 4] = rh4[b * 256 + j];
        }
        __syncthreads();

        // ---- Phase B: hbar ----
        gate_phase<8, 16>(wsm, xh_s, pbuf, warp, lane);
        __syncthreads();
        if (tid < 64) {
            int b = tid >> 3, j = tid & 7;
            float s = 0.f;
#pragma unroll
            for (int w = 0; w < 8; w++) s += pbuf[w * 128 + b * 16 + j];
            float hbar = tanhf(s + bsm[16 + j]);
            int c = colbase + j;
            float hprev = (t == 0) ? start[c] : g_h[b * NHID + c];
            float z = zsm[b * 8 + j];
            float hn = hprev + z * (hbar - hprev);
            g_h[b * NHID + c] = hn;
            g_hs[(size_t)(b * TSTEPS + t) * NHID + c] = __float2half(hn);
        }
        grid_barrier();
    }
}

// ---------------------------------------------------------------------------
// fp32 -> fp16 weight conversion
// ---------------------------------------------------------------------------
__global__ void cvt_half2(const float2* __restrict__ src, __half2* __restrict__ dst, int n2) {
    int i = blockIdx.x * blockDim.x + threadIdx.x;
    int stride = gridDim.x * blockDim.x;
    for (; i < n2; i += stride) {
        float2 v = src[i];
        dst[i] = __floats2half2_rn(v.x, v.y);
    }
}

// ---------------------------------------------------------------------------
// LM head GEMM: C[4096,32000] = A[4096,1024](f16) * B[1024,32000](f16) + bias
// ---------------------------------------------------------------------------
__device__ __forceinline__ void mma16816(float& c0, float& c1, float& c2, float& c3,
                                         unsigned a0, unsigned a1, unsigned a2, unsigned a3,
                                         unsigned b0, unsigned b1) {
    asm volatile(
        "mma.sync.aligned.m16n8k16.row.col.f32.f16.f16.f32 "
        "{%0,%1,%2,%3}, {%4,%5,%6,%7}, {%8,%9}, {%0,%1,%2,%3};\n"
        : "+f"(c0), "+f"(c1), "+f"(c2), "+f"(c3)
        : "r"(a0), "r"(a1), "r"(a2), "r"(a3), "r"(b0), "r"(b1));
}

#define AS_STRIDE 40
#define BS_STRIDE 42

__global__ void __launch_bounds__(256)
lmhead_kernel(const __half* __restrict__ A, const __half* __restrict__ Bw,
              const float* __restrict__ bias, float* __restrict__ C) {
    const int bx = blockIdx.x, by = blockIdx.y;
    const int tid = threadIdx.x, warp = tid >> 5, lane = tid & 31;
    const int wm = warp >> 2, wn = warp & 3;
    __shared__ __half As[128 * AS_STRIDE];
    __shared__ __half Bs[128 * BS_STRIDE];

    float acc[4][4][4];
#pragma unroll
    for (int a = 0; a < 4; a++)
#pragma unroll
        for (int b = 0; b < 4; b++)
#pragma unroll
            for (int c = 0; c < 4; c++) acc[a][b][c] = 0.f;

    const int m0 = by * 128, n0 = bx * 128;

    for (int k0 = 0; k0 < NHID; k0 += 32) {
#pragma unroll
        for (int i = tid; i < 512; i += 256) {
            int row = i >> 2, seg = i & 3;
            *(uint4*)&As[row * AS_STRIDE + seg * 8] =
                *(const uint4*)&A[(size_t)(m0 + row) * NHID + k0 + seg * 8];
        }
#pragma unroll
        for (int i = tid; i < 2048; i += 256) {
            int k = i >> 6, np = i & 63;
            __half2 h2 = *(const __half2*)(Bw + (size_t)(k0 + k) * VOCAB + n0 + np * 2);
            Bs[(np * 2)     * BS_STRIDE + k] = __low2half(h2);
            Bs[(np * 2 + 1) * BS_STRIDE + k] = __high2half(h2);
        }
        __syncthreads();

#pragma unroll
        for (int kk = 0; kk < 2; kk++) {
            unsigned a[4][4], b[4][2];
            const int kc = kk * 16 + (lane & 3) * 2;
            const int r  = lane >> 2;
#pragma unroll
            for (int mt = 0; mt < 4; mt++) {
                int rr = wm * 64 + mt * 16 + r;
                a[mt][0] = *(const unsigned*)&As[rr * AS_STRIDE + kc];
                a[mt][1] = *(const unsigned*)&As[(rr + 8) * AS_STRIDE + kc];
                a[mt][2] = *(const unsigned*)&As[rr * AS_STRIDE + kc + 8];
                a[mt][3] = *(const unsigned*)&As[(rr + 8) * AS_STRIDE + kc + 8];
            }
#pragma unroll
            for (int nt = 0; nt < 4; nt++) {
                int nn = wn * 32 + nt * 8 + r;
                b[nt][0] = *(const unsigned*)&Bs[nn * BS_STRIDE + kc];
                b[nt][1] = *(const unsigned*)&Bs[nn * BS_STRIDE + kc + 8];
            }
#pragma unroll
            for (int mt = 0; mt < 4; mt++)
#pragma unroll
                for (int nt = 0; nt < 4; nt++)
                    mma16816(acc[mt][nt][0], acc[mt][nt][1], acc[mt][nt][2], acc[mt][nt][3],
                             a[mt][0], a[mt][1], a[mt][2], a[mt][3], b[nt][0], b[nt][1]);
        }
        __syncthreads();
    }

#pragma unroll
    for (int mt = 0; mt < 4; mt++) {
#pragma unroll
        for (int nt = 0; nt < 4; nt++) {
            int gr = m0 + wm * 64 + mt * 16 + (lane >> 2);
            int gc = n0 + wn * 32 + nt * 8 + (lane & 3) * 2;
            float b0 = bias[gc], b1 = bias[gc + 1];
            float2 v0 = make_float2(acc[mt][nt][0] + b0, acc[mt][nt][1] + b1);
            float2 v1 = make_float2(acc[mt][nt][2] + b0, acc[mt][nt][3] + b1);
            *(float2*)&C[(size_t)gr * VOCAB + gc]       = v0;
            *(float2*)&C[(size_t)(gr + 8) * VOCAB + gc] = v1;
        }
    }
}

// ---------------------------------------------------------------------------
// Loss: per-row online logsumexp, mean NLL via atomicAdd
// ---------------------------------------------------------------------------
__global__ void __launch_bounds__(256)
loss_kernel(const float* __restrict__ logits, const int* __restrict__ targets,
            float* __restrict__ out_loss) {
    const int row = blockIdx.x;
    const float* lr = logits + (size_t)row * VOCAB;
    const int tid = threadIdx.x;

    float m = -1e30f, s = 0.f;
    for (int i = tid; i < VOCAB; i += 256) {
        float v = lr[i];
        float nm = fmaxf(m, v);
        s = s * __expf(m - nm) + __expf(v - nm);
        m = nm;
    }
    __shared__ float sm_m[256], sm_s[256];
    sm_m[tid] = m; sm_s[tid] = s;
    __syncthreads();
    for (int off = 128; off > 0; off >>= 1) {
        if (tid < off) {
            float m2 = sm_m[tid + off], s2 = sm_s[tid + off];
            float m1 = sm_m[tid],       s1 = sm_s[tid];
            float nm = fmaxf(m1, m2);
            sm_s[tid] = s1 * __expf(m1 - nm) + s2 * __expf(m2 - nm);
            sm_m[tid] = nm;
        }
        __syncthreads();
    }
    if (tid == 0) {
        float lse = sm_m[0] + logf(sm_s[0]);
        float tl  = lr[targets[row]];
        atomicAdd(out_loss, (lse - tl) * (1.0f / (float)NROWS));
    }
}

// ---------------------------------------------------------------------------
// Host entry — all __device__ globals resolved via cudaGetSymbolAddress.
// ---------------------------------------------------------------------------
extern "C" void kernel_launch(void* const* d_in, const int* in_sizes, int n_in,
                              void* d_out, int out_size) {
    const int*   idx   = (const int*)d_in[0];
    const int*   tgt   = (const int*)d_in[1];
    const float* wte   = (const float*)d_in[2];
    const float* start = (const float*)d_in[3];
    const float* Wz    = (const float*)d_in[4];
    const float* bz    = (const float*)d_in[5];
    const float* Wr    = (const float*)d_in[6];
    const float* br    = (const float*)d_in[7];
    const float* Wh    = (const float*)d_in[8];
    const float* bh    = (const float*)d_in[9];
    const float* lmW   = (const float*)d_in[10];
    const float* lmb   = (const float*)d_in[11];

    // Resolve device addresses of globals (NOT host-shadow name decay).
    void *p_hs = nullptr, *p_wlm = nullptr, *p_fb = nullptr;
    cudaGetSymbolAddress(&p_hs,  g_hs);
    cudaGetSymbolAddress(&p_wlm, g_wlm);
    cudaGetSymbolAddress(&p_fb,  g_logits_fb);
    __half* d_hs  = (__half*)p_hs;
    __half* d_wlm = (__half*)p_wlm;
    float*  d_fb  = (float*)p_fb;

    cudaFuncSetAttribute(gru_kernel, cudaFuncAttributeMaxDynamicSharedMemorySize,
                         GRU_SMEM_BYTES);

    // 1) convert lm head weights to fp16
    cvt_half2<<<4096, 256>>>((const float2*)lmW, (__half2*)d_wlm, (NHID * VOCAB) / 2);

    // 2) persistent GRU scan
    gru_kernel<<<GRU_BLOCKS, GRU_THREADS, GRU_SMEM_BYTES>>>(idx, wte, start,
                                                            Wz, bz, Wr, br, Wh, bh);

    // 3) LM head
    const long long NL = (long long)NROWS * VOCAB;  // 131,072,000
    float* fo = (float*)d_out;
    float* logits = ((long long)out_size >= NL) ? fo : d_fb;
    lmhead_kernel<<<dim3(VOCAB / 128, NROWS / 128), 256>>>(d_hs, d_wlm, lmb, logits);

    // 4) loss (if the output buffer has a slot for it)
    float* loss_ptr = nullptr;
    if ((long long)out_size >= NL + 1)      loss_ptr = fo + NL;   // logits + loss
    else if ((long long)out_size < NL)      loss_ptr = fo;        // loss only
    if (loss_ptr) {
        cudaMemsetAsync(loss_ptr, 0, sizeof(float));
        loss_kernel<<<NROWS, 256>>>(logits, tgt, loss_ptr);
    }
}